// round 3
// baseline (speedup 1.0000x reference)
#include <cuda_runtime.h>

// Fused conv1 -> conv2 -> SIFT128 -> linear -> softmax, one CTA/image.
// Round 3: packed f32x2 FMA (FFMA2) for conv1/conv2 with pre-splatted weights.

__constant__ float c_b1[32];
__constant__ float c_b2[3];
__constant__ float c_bl[10];

// packed (w,w) splat table: [0,288) conv1, [288,1152) conv2 (OIHW order)
__device__ __align__(16) float2 g_wpk[1152];

typedef unsigned long long u64;

__device__ __forceinline__ void fma2(u64& d, u64 a, u64 b) {
    asm("fma.rn.f32x2 %0, %1, %2, %0;" : "+l"(d) : "l"(a), "l"(b));
}
__device__ __forceinline__ u64 pk2(float lo, float hi) {
    u64 r; asm("mov.b64 %0, {%1, %2};" : "=l"(r) : "f"(lo), "f"(hi)); return r;
}
__device__ __forceinline__ float2 upk(u64 v) {
    float2 f; asm("mov.b64 {%0, %1}, %2;" : "=f"(f.x), "=f"(f.y) : "l"(v)); return f;
}

// shared layout (floats)
#define SM_XS      0                   // 28 rows, stride 30 -> 840
#define SM_A1      840                 // 8-ch chunk, 26x26 stride 26 -> 5408
#define SM_A2P     (SM_A1 + 5408)      // 3 ch padded 26x26 -> 2028
#define SM_CELLS   (SM_A2P + 2028)     // 384
#define SM_NORMS   (SM_CELLS + 384)    // 4
#define SM_LOGITS  (SM_NORMS + 4)      // 12
#define SM_WPK     8676                // 1152 float2 = 2304 floats (16B aligned)
#define SM_FLOATS  (SM_WPK + 2304)     // 10980 floats = 43920 B

__global__ void pack_weights(const float* __restrict__ W1,
                             const float* __restrict__ W2)
{
    int i = threadIdx.x + blockIdx.x * blockDim.x;
    if (i < 288)  g_wpk[i]       = make_float2(W1[i], W1[i]);
    if (i < 864)  g_wpk[288 + i] = make_float2(W2[i], W2[i]);
}

__global__ __launch_bounds__(256, 4)
void fused_sift_net(const float* __restrict__ x,
                    const float* __restrict__ Wl,
                    float* __restrict__ out)
{
    extern __shared__ float sm[];
    const int tid = threadIdx.x;
    const int img = blockIdx.x;

    // ---------------- Phase 0: image load, weight stage, zero bufs ---------
    {
        const float4* xg = (const float4*)(x + (size_t)img * 784);
        for (int i4 = tid; i4 < 196; i4 += 256) {
            float4 v = __ldg(&xg[i4]);
            int li = i4 * 4;
            int r = li / 28, c = li % 28;
            float* p = &sm[SM_XS + r * 30 + c];
            *(float2*)p       = make_float2(v.x, v.y);
            *(float2*)(p + 2) = make_float2(v.z, v.w);
        }
        const float4* gw = (const float4*)g_wpk;
        float4* swp = (float4*)&sm[SM_WPK];
        for (int i = tid; i < 576; i += 256) swp[i] = __ldg(&gw[i]);
        for (int i = tid; i < 2028; i += 256) sm[SM_A2P + i] = 0.0f;
        for (int i = tid; i < 400; i += 256)
            if (SM_CELLS + i < SM_LOGITS) sm[SM_CELLS + i] = 0.0f;
    }

    // conv2 persistent accumulators: thread = 2 out-rows x 2 out-cols
    const int c2rp = tid / 12;          // 0..11 (valid when tid<144)
    const int c2sp = tid % 12;          // 0..11
    u64 acc[3][2];
    if (tid < 144) {
#pragma unroll
        for (int oc = 0; oc < 3; oc++) {
            u64 bp = pk2(c_b2[oc], c_b2[oc]);
            acc[oc][0] = bp; acc[oc][1] = bp;
        }
    }

    const u64* wpk = (const u64*)&sm[SM_WPK];

    // ---------------- Phases 1-2: 4 chunks of 8 channels --------------------
    for (int chunk = 0; chunk < 4; chunk++) {
        __syncthreads();

        // conv1: 208 tasks = 8 channels x 26 rows, px-pair FFMA2
        if (tid < 208) {
            int chl = tid / 26;             // chunk-local channel 0..7
            int row = tid % 26;
            int ch  = chunk * 8 + chl;
            const u64* ws = wpk + ch * 9;
            u64 w0 = ws[0], w1 = ws[1], w2 = ws[2];
            u64 w3 = ws[3], w4 = ws[4], w5 = ws[5];
            u64 w6 = ws[6], w7 = ws[7], w8 = ws[8];
            float bv = c_b1[ch];
            u64 bp = pk2(bv, bv);
            const float* xr = &sm[SM_XS + row * 30];
            float2 cur0 = *(const float2*)(xr);
            float2 cur1 = *(const float2*)(xr + 30);
            float2 cur2 = *(const float2*)(xr + 60);
            float* o = &sm[SM_A1 + chl * 676 + row * 26];
#pragma unroll
            for (int s = 0; s < 13; s++) {
                int c = 2 * s;
                float2 n0 = *(const float2*)(xr + c + 2);
                float2 n1 = *(const float2*)(xr + 30 + c + 2);
                float2 n2 = *(const float2*)(xr + 60 + c + 2);
                u64 a = bp;
                fma2(a, pk2(cur0.x, cur0.y), w0);
                fma2(a, pk2(cur0.y, n0.x),   w1);
                fma2(a, pk2(n0.x,   n0.y),   w2);
                fma2(a, pk2(cur1.x, cur1.y), w3);
                fma2(a, pk2(cur1.y, n1.x),   w4);
                fma2(a, pk2(n1.x,   n1.y),   w5);
                fma2(a, pk2(cur2.x, cur2.y), w6);
                fma2(a, pk2(cur2.y, n2.x),   w7);
                fma2(a, pk2(n2.x,   n2.y),   w8);
                float2 f = upk(a);
                *(float2*)(o + c) = make_float2(fmaxf(f.x, 0.0f), fmaxf(f.y, 0.0f));
                cur0 = n0; cur1 = n1; cur2 = n2;
            }
        }
        __syncthreads();

        // conv2: accumulate 8 input channels, px-pair FFMA2
        if (tid < 144) {
            const float* a1b = &sm[SM_A1 + c2rp * 52 + c2sp * 2];
#pragma unroll
            for (int ic = 0; ic < 8; ic++) {
                const float* ap = a1b + ic * 676;
                // rows 2rp .. 2rp+3, operand pairs P(t=0), M(t=1), Q(t=2)
                u64 P[4], M[4], Q[4];
#pragma unroll
                for (int r = 0; r < 4; r++) {
                    float2 fa = *(const float2*)(ap + r * 26);
                    float2 fb = *(const float2*)(ap + r * 26 + 2);
                    P[r] = pk2(fa.x, fa.y);
                    M[r] = pk2(fa.y, fb.x);
                    Q[r] = pk2(fb.x, fb.y);
                }
                const u64* wbase = wpk + 288 + (chunk * 8 + ic) * 9;
#pragma unroll
                for (int oc = 0; oc < 3; oc++) {
                    const u64* wo = wbase + oc * 288;
#pragma unroll
                    for (int dy = 0; dy < 3; dy++) {
                        u64 wa = wo[dy * 3 + 0];
                        u64 wb = wo[dy * 3 + 1];
                        u64 wc = wo[dy * 3 + 2];
                        fma2(acc[oc][0], P[dy],     wa);
                        fma2(acc[oc][0], M[dy],     wb);
                        fma2(acc[oc][0], Q[dy],     wc);
                        fma2(acc[oc][1], P[dy + 1], wa);
                        fma2(acc[oc][1], M[dy + 1], wb);
                        fma2(acc[oc][1], Q[dy + 1], wc);
                    }
                }
            }
        }
    }

    // write conv2 outputs into padded tile (scalar stores, odd col offset)
    if (tid < 144) {
#pragma unroll
        for (int oc = 0; oc < 3; oc++)
#pragma unroll
            for (int ro = 0; ro < 2; ro++) {
                float2 f = upk(acc[oc][ro]);
                float* dst = &sm[SM_A2P + oc * 676 + (c2rp * 2 + ro + 1) * 26 + (c2sp * 2 + 1)];
                dst[0] = f.x;
                dst[1] = f.y;
            }
    }
    __syncthreads();

    // ---------------- Phase 3: SIFT, register histograms --------------------
    if (tid < 192) {
        const float CS[8] = { 0.92387953f,  0.38268343f, -0.38268343f, -0.92387953f,
                             -0.92387953f, -0.38268343f,  0.38268343f,  0.92387953f};
        const float SN[8] = { 0.38268343f,  0.92387953f,  0.92387953f,  0.38268343f,
                             -0.38268343f, -0.92387953f, -0.92387953f, -0.38268343f};
        int p    = tid / 64;
        int rem  = tid % 64;
        int cell = rem >> 2;
        int quad = rem & 3;
        int r0 = (cell >> 2) * 6 + (quad >> 1) * 3;
        int c0 = (cell & 3) * 6 + (quad & 1) * 3;
        const float* ap = &sm[SM_A2P + p * 676 + r0 * 26 + c0];
        float pt[5][5];
#pragma unroll
        for (int i = 0; i < 5; i++)
#pragma unroll
            for (int j = 0; j < 5; j++) pt[i][j] = ap[i * 26 + j];

        float hist[8] = {0,0,0,0,0,0,0,0};
#pragma unroll
        for (int i = 0; i < 3; i++) {
#pragma unroll
            for (int j = 0; j < 3; j++) {
                float Ix = (pt[i][j+2] - pt[i][j])
                         + 2.0f * (pt[i+1][j+2] - pt[i+1][j])
                         + (pt[i+2][j+2] - pt[i+2][j]);
                float Iy = (pt[i+2][j] - pt[i][j])
                         + 2.0f * (pt[i+2][j+1] - pt[i][j+1])
                         + (pt[i+2][j+2] - pt[i][j+2]);
                float mag = sqrtf(Ix * Ix + Iy * Iy + 1e-12f);
                float ck[8];
                float cmax = -1e30f;
#pragma unroll
                for (int k = 0; k < 8; k++) {
                    ck[k] = CS[k] * Ix + SN[k] * Iy;
                    cmax = fmaxf(cmax, ck[k]);
                }
#pragma unroll
                for (int k = 0; k < 8; k++)
                    hist[k] += (ck[k] == cmax) ? mag : 0.0f;
            }
        }
#pragma unroll
        for (int k = 0; k < 8; k++) {
            float v = hist[k];
            v += __shfl_xor_sync(0xffffffffu, v, 1);
            v += __shfl_xor_sync(0xffffffffu, v, 2);
            if (quad == 0)
                sm[SM_CELLS + p * 128 + k * 16 + cell] = v;
        }
    }
    __syncthreads();

    // ---------------- Phase 4: norms + pow 0.9 ------------------------------
    if (tid < 96) {
        int w = tid >> 5, lane = tid & 31;
        const float* cp = &sm[SM_CELLS + w * 128];
        float s = 0.0f;
#pragma unroll
        for (int j = 0; j < 4; j++) {
            float v = cp[lane + 32 * j];
            s = fmaf(v, v, s);
        }
#pragma unroll
        for (int d = 16; d; d >>= 1)
            s += __shfl_xor_sync(0xffffffffu, s, d);
        if (lane == 0) sm[SM_NORMS + w] = sqrtf(s);
    }
    __syncthreads();
    {
        int i = tid;
        if (i < 384) {
            float v = sm[SM_CELLS + i];
            float f = v / (sm[SM_NORMS + (i >> 7)] + 1e-8f);
            sm[SM_CELLS + i] = powf(f + 1e-8f, 0.9f);
        }
        i = tid + 256;
        if (i < 384) {
            float v = sm[SM_CELLS + i];
            float f = v / (sm[SM_NORMS + (i >> 7)] + 1e-8f);
            sm[SM_CELLS + i] = powf(f + 1e-8f, 0.9f);
        }
    }
    __syncthreads();

    // ---------------- Phase 5: 384x10 linear --------------------------------
    {
        int w = tid >> 5, lane = tid & 31;
#pragma unroll
        for (int rep = 0; rep < 2; rep++) {
            int o = w + rep * 8;
            if (o < 10) {
                float s = 0.0f;
                const float* wrow = Wl + o * 384;
                for (int i = lane; i < 384; i += 32)
                    s = fmaf(sm[SM_CELLS + i], __ldg(&wrow[i]), s);
#pragma unroll
                for (int d = 16; d; d >>= 1)
                    s += __shfl_xor_sync(0xffffffffu, s, d);
                if (lane == 0) sm[SM_LOGITS + o] = s + c_bl[o];
            }
        }
    }
    __syncthreads();

    // ---------------- Phase 6: relu + softmax -------------------------------
    if (tid < 32) {
        float v = (tid < 10) ? fmaxf(sm[SM_LOGITS + tid], 0.0f) : -1e30f;
        float m = v;
#pragma unroll
        for (int d = 16; d; d >>= 1)
            m = fmaxf(m, __shfl_xor_sync(0xffffffffu, m, d));
        float e = (tid < 10) ? expf(v - m) : 0.0f;
        float ssum = e;
#pragma unroll
        for (int d = 16; d; d >>= 1)
            ssum += __shfl_xor_sync(0xffffffffu, ssum, d);
        if (tid < 10) out[(size_t)img * 10 + tid] = e / ssum;
    }
}

extern "C" void kernel_launch(void* const* d_in, const int* in_sizes, int n_in,
                              void* d_out, int out_size)
{
    const float* x  = (const float*)d_in[0];
    const float* W1 = (const float*)d_in[1];
    const float* b1 = (const float*)d_in[2];
    const float* W2 = (const float*)d_in[3];
    const float* b2 = (const float*)d_in[4];
    const float* Wl = (const float*)d_in[5];
    const float* bl = (const float*)d_in[6];

    int nimg = in_sizes[0] / 784;

    cudaMemcpyToSymbolAsync(c_b1, b1, 32 * sizeof(float), 0, cudaMemcpyDeviceToDevice, 0);
    cudaMemcpyToSymbolAsync(c_b2, b2,  3 * sizeof(float), 0, cudaMemcpyDeviceToDevice, 0);
    cudaMemcpyToSymbolAsync(c_bl, bl, 10 * sizeof(float), 0, cudaMemcpyDeviceToDevice, 0);

    pack_weights<<<4, 256>>>(W1, W2);

    size_t smem = SM_FLOATS * sizeof(float);
    cudaFuncSetAttribute(fused_sift_net,
                         cudaFuncAttributeMaxDynamicSharedMemorySize, (int)smem);

    fused_sift_net<<<nimg, 256, smem>>>(x, Wl, (float*)d_out);
}

// round 4
// speedup vs baseline: 1.1978x; 1.1978x over previous
#include <cuda_runtime.h>

// Fused conv1 -> conv2 -> SIFT128 -> linear -> softmax, one CTA/image.
// Round 4: FFMA2 with operands born packed (splat image for conv1,
// channel-pair-interleaved a1 for conv2). No repacking MOVs.

__constant__ float c_b1[32];
__constant__ float c_b2[3];
__constant__ float c_bl[10];

typedef unsigned long long u64;

// packed weight tables: [0,144) conv1 (w_even,w_odd) pairs; [144,576) conv2
__device__ __align__(16) float2 g_wpk[576];

__device__ __forceinline__ void fma2(u64& d, u64 a, u64 b) {
    asm("fma.rn.f32x2 %0, %1, %2, %0;" : "+l"(d) : "l"(a), "l"(b));
}
__device__ __forceinline__ u64 pk2(float lo, float hi) {
    u64 r; asm("mov.b64 %0, {%1, %2};" : "=l"(r) : "f"(lo), "f"(hi)); return r;
}
__device__ __forceinline__ float2 upk(u64 v) {
    float2 f; asm("mov.b64 {%0, %1}, %2;" : "=f"(f.x), "=f"(f.y) : "l"(v)); return f;
}

// shared layout (floats)
#define SM_XSPL    0                    // 28 rows x 30 cols splat pairs -> 1680
#define SM_A1P     1680                 // 4 ch-pairs x 26x26 float2 -> 5408
#define SM_A2P     (SM_A1P + 5408)      // 3 ch padded 26x26 -> 2028
#define SM_CELLS   (SM_A2P + 2028)      // 384
#define SM_NORMS   (SM_CELLS + 384)     // 4
#define SM_LOGITS  (SM_NORMS + 4)       // 12
#define SM_WPK     (SM_LOGITS + 12)     // 9516 (16B aligned): 576 u64 = 1152 fl
#define SM_FLOATS  (SM_WPK + 1152)      // 10668 floats = 42672 B

__global__ void pack_weights(const float* __restrict__ W1,
                             const float* __restrict__ W2)
{
    int i = threadIdx.x + blockIdx.x * blockDim.x;
    if (i < 144) {
        int p = i / 9, k = i % 9;
        g_wpk[i] = make_float2(W1[(2 * p) * 9 + k], W1[(2 * p + 1) * 9 + k]);
    } else if (i < 576) {
        int j = i - 144;
        int oc = j / 144, r = j % 144;
        int icp = r / 9, tap = r % 9;
        g_wpk[i] = make_float2(W2[oc * 288 + (2 * icp) * 9 + tap],
                               W2[oc * 288 + (2 * icp + 1) * 9 + tap]);
    }
}

__global__ __launch_bounds__(256, 3)
void fused_sift_net(const float* __restrict__ x,
                    const float* __restrict__ Wl,
                    float* __restrict__ out)
{
    extern __shared__ float sm[];
    const int tid = threadIdx.x;
    const int img = blockIdx.x;

    // ---------------- Phase 0: splat image, stage weights, zero a2 ---------
    {
        const float4* xg = (const float4*)(x + (size_t)img * 784);
        float4* xs = (float4*)&sm[SM_XSPL];
        for (int i4 = tid; i4 < 196; i4 += 256) {
            float4 v = __ldg(&xg[i4]);
            int li = i4 * 4;
            int r = li / 28, c = li % 28;          // c multiple of 4
            int fi = (r * 30 + c) >> 1;            // float4 index (16B aligned)
            xs[fi]     = make_float4(v.x, v.x, v.y, v.y);
            xs[fi + 1] = make_float4(v.z, v.z, v.w, v.w);
        }
        const float4* gw = (const float4*)g_wpk;
        float4* swp = (float4*)&sm[SM_WPK];
        for (int i = tid; i < 288; i += 256) swp[i] = __ldg(&gw[i]);
        for (int i = tid; i < 2028; i += 256) sm[SM_A2P + i] = 0.0f;
    }

    // conv2 persistent accumulators: 96 threads, 1 out-row x 6-px strip
    const int c2row = tid >> 2;          // 0..23 (valid when tid<96)
    const int c2xb  = (tid & 3) * 6;     // 0,6,12,18
    u64 acc[3][6];
    if (tid < 96) {
#pragma unroll
        for (int oc = 0; oc < 3; oc++) {
            u64 bp = pk2(c_b2[oc], 0.0f);    // bias once in lo half
#pragma unroll
            for (int j = 0; j < 6; j++) acc[oc][j] = bp;
        }
    }

    const u64* wpk1 = (const u64*)&sm[SM_WPK];
    const u64* wpk2 = wpk1 + 144;
    const u64* xspl = (const u64*)&sm[SM_XSPL];
    u64* a1u = (u64*)&sm[SM_A1P];

    // ---------------- Phases 1-2: 4 chunks of 8 channels (4 pairs) ---------
    for (int chunk = 0; chunk < 4; chunk++) {
        __syncthreads();

        // conv1: 208 tasks = 4 pairs x 26 rows x 2 halves (13 cols each)
        if (tid < 208) {
            int pl   = tid / 52;
            int tt   = tid % 52;
            int row  = tt >> 1;
            int half = tt & 1;
            int gp   = chunk * 4 + pl;
            const u64* ws = wpk1 + gp * 9;
            u64 w0 = ws[0], w1 = ws[1], w2 = ws[2];
            u64 w3 = ws[3], w4 = ws[4], w5 = ws[5];
            u64 w6 = ws[6], w7 = ws[7], w8 = ws[8];
            u64 bp = pk2(c_b1[2 * gp], c_b1[2 * gp + 1]);
            const u64* xr = xspl + row * 30 + half * 13;
            u64 t00 = xr[0],  t01 = xr[1];
            u64 t10 = xr[30], t11 = xr[31];
            u64 t20 = xr[60], t21 = xr[61];
            float2* o = (float2*)a1u + pl * 676 + row * 26 + half * 13;
#pragma unroll
            for (int s = 0; s < 13; s++) {
                u64 n0 = xr[s + 2], n1 = xr[s + 32], n2 = xr[s + 62];
                u64 a = bp;
                fma2(a, t00, w0); fma2(a, t01, w1); fma2(a, n0, w2);
                fma2(a, t10, w3); fma2(a, t11, w4); fma2(a, n1, w5);
                fma2(a, t20, w6); fma2(a, t21, w7); fma2(a, n2, w8);
                float2 f = upk(a);
                o[s] = make_float2(fmaxf(f.x, 0.0f), fmaxf(f.y, 0.0f));
                t00 = t01; t01 = n0;
                t10 = t11; t11 = n1;
                t20 = t21; t21 = n2;
            }
        }
        __syncthreads();

        // conv2: 4 input-channel pairs, acts via aligned LDS.64
        if (tid < 96) {
#pragma unroll
            for (int icp = 0; icp < 4; icp++) {
                const u64* ap = a1u + icp * 676 + c2row * 26 + c2xb;
                int gicp = chunk * 4 + icp;
#pragma unroll
                for (int dy = 0; dy < 3; dy++) {
                    u64 v[8];
#pragma unroll
                    for (int j = 0; j < 8; j++) v[j] = ap[dy * 26 + j];
#pragma unroll
                    for (int oc = 0; oc < 3; oc++) {
                        const u64* wo = wpk2 + (oc * 16 + gicp) * 9 + dy * 3;
                        u64 wa = wo[0], wb = wo[1], wc = wo[2];
#pragma unroll
                        for (int j = 0; j < 6; j++) {
                            fma2(acc[oc][j], v[j],     wa);
                            fma2(acc[oc][j], v[j + 1], wb);
                            fma2(acc[oc][j], v[j + 2], wc);
                        }
                    }
                }
            }
        }
    }

    // conv2 outputs -> padded tile (scalar = lo + hi)
    if (tid < 96) {
#pragma unroll
        for (int oc = 0; oc < 3; oc++) {
            float* dst = &sm[SM_A2P + oc * 676 + (c2row + 1) * 26 + (c2xb + 1)];
#pragma unroll
            for (int j = 0; j < 6; j++) {
                float2 f = upk(acc[oc][j]);
                dst[j] = f.x + f.y;
            }
        }
    }
    __syncthreads();

    // ---------------- Phase 3: SIFT, register histograms --------------------
    if (tid < 192) {
        const float CS[8] = { 0.92387953f,  0.38268343f, -0.38268343f, -0.92387953f,
                             -0.92387953f, -0.38268343f,  0.38268343f,  0.92387953f};
        const float SN[8] = { 0.38268343f,  0.92387953f,  0.92387953f,  0.38268343f,
                             -0.38268343f, -0.92387953f, -0.92387953f, -0.38268343f};
        int p    = tid / 64;
        int rem  = tid % 64;
        int cell = rem >> 2;
        int quad = rem & 3;
        int r0 = (cell >> 2) * 6 + (quad >> 1) * 3;
        int c0 = (cell & 3) * 6 + (quad & 1) * 3;
        const float* ap = &sm[SM_A2P + p * 676 + r0 * 26 + c0];
        float pt[5][5];
#pragma unroll
        for (int i = 0; i < 5; i++)
#pragma unroll
            for (int j = 0; j < 5; j++) pt[i][j] = ap[i * 26 + j];

        float hist[8] = {0,0,0,0,0,0,0,0};
#pragma unroll
        for (int i = 0; i < 3; i++) {
#pragma unroll
            for (int j = 0; j < 3; j++) {
                float Ix = (pt[i][j+2] - pt[i][j])
                         + 2.0f * (pt[i+1][j+2] - pt[i+1][j])
                         + (pt[i+2][j+2] - pt[i+2][j]);
                float Iy = (pt[i+2][j] - pt[i][j])
                         + 2.0f * (pt[i+2][j+1] - pt[i][j+1])
                         + (pt[i+2][j+2] - pt[i][j+2]);
                float mag = sqrtf(Ix * Ix + Iy * Iy + 1e-12f);
                float ck[8];
                float cmax = -1e30f;
#pragma unroll
                for (int k = 0; k < 8; k++) {
                    ck[k] = CS[k] * Ix + SN[k] * Iy;
                    cmax = fmaxf(cmax, ck[k]);
                }
#pragma unroll
                for (int k = 0; k < 8; k++)
                    hist[k] += (ck[k] == cmax) ? mag : 0.0f;
            }
        }
#pragma unroll
        for (int k = 0; k < 8; k++) {
            float v = hist[k];
            v += __shfl_xor_sync(0xffffffffu, v, 1);
            v += __shfl_xor_sync(0xffffffffu, v, 2);
            if (quad == 0)
                sm[SM_CELLS + p * 128 + k * 16 + cell] = v;
        }
    }
    __syncthreads();

    // ---------------- Phase 4: norms + pow 0.9 ------------------------------
    if (tid < 96) {
        int w = tid >> 5, lane = tid & 31;
        const float* cp = &sm[SM_CELLS + w * 128];
        float s = 0.0f;
#pragma unroll
        for (int j = 0; j < 4; j++) {
            float v = cp[lane + 32 * j];
            s = fmaf(v, v, s);
        }
#pragma unroll
        for (int d = 16; d; d >>= 1)
            s += __shfl_xor_sync(0xffffffffu, s, d);
        if (lane == 0) sm[SM_NORMS + w] = sqrtf(s);
    }
    __syncthreads();
    {
        int i = tid;
        if (i < 384) {
            float v = sm[SM_CELLS + i];
            float f = v / (sm[SM_NORMS + (i >> 7)] + 1e-8f);
            sm[SM_CELLS + i] = powf(f + 1e-8f, 0.9f);
        }
        i = tid + 256;
        if (i < 384) {
            float v = sm[SM_CELLS + i];
            float f = v / (sm[SM_NORMS + (i >> 7)] + 1e-8f);
            sm[SM_CELLS + i] = powf(f + 1e-8f, 0.9f);
        }
    }
    __syncthreads();

    // ---------------- Phase 5: 384x10 linear --------------------------------
    {
        int w = tid >> 5, lane = tid & 31;
#pragma unroll
        for (int rep = 0; rep < 2; rep++) {
            int o = w + rep * 8;
            if (o < 10) {
                float s = 0.0f;
                const float* wrow = Wl + o * 384;
                for (int i = lane; i < 384; i += 32)
                    s = fmaf(sm[SM_CELLS + i], __ldg(&wrow[i]), s);
#pragma unroll
                for (int d = 16; d; d >>= 1)
                    s += __shfl_xor_sync(0xffffffffu, s, d);
                if (lane == 0) sm[SM_LOGITS + o] = s + c_bl[o];
            }
        }
    }
    __syncthreads();

    // ---------------- Phase 6: relu + softmax -------------------------------
    if (tid < 32) {
        float v = (tid < 10) ? fmaxf(sm[SM_LOGITS + tid], 0.0f) : -1e30f;
        float m = v;
#pragma unroll
        for (int d = 16; d; d >>= 1)
            m = fmaxf(m, __shfl_xor_sync(0xffffffffu, m, d));
        float e = (tid < 10) ? expf(v - m) : 0.0f;
        float ssum = e;
#pragma unroll
        for (int d = 16; d; d >>= 1)
            ssum += __shfl_xor_sync(0xffffffffu, ssum, d);
        if (tid < 10) out[(size_t)img * 10 + tid] = e / ssum;
    }
}

extern "C" void kernel_launch(void* const* d_in, const int* in_sizes, int n_in,
                              void* d_out, int out_size)
{
    const float* x  = (const float*)d_in[0];
    const float* W1 = (const float*)d_in[1];
    const float* b1 = (const float*)d_in[2];
    const float* W2 = (const float*)d_in[3];
    const float* b2 = (const float*)d_in[4];
    const float* Wl = (const float*)d_in[5];
    const float* bl = (const float*)d_in[6];

    int nimg = in_sizes[0] / 784;

    cudaMemcpyToSymbolAsync(c_b1, b1, 32 * sizeof(float), 0, cudaMemcpyDeviceToDevice, 0);
    cudaMemcpyToSymbolAsync(c_b2, b2,  3 * sizeof(float), 0, cudaMemcpyDeviceToDevice, 0);
    cudaMemcpyToSymbolAsync(c_bl, bl, 10 * sizeof(float), 0, cudaMemcpyDeviceToDevice, 0);

    pack_weights<<<3, 256>>>(W1, W2);

    size_t smem = SM_FLOATS * sizeof(float);
    cudaFuncSetAttribute(fused_sift_net,
                         cudaFuncAttributeMaxDynamicSharedMemorySize, (int)smem);

    fused_sift_net<<<nimg, 256, smem>>>(x, Wl, (float*)d_out);
}